// round 8
// baseline (speedup 1.0000x reference)
#include <cuda_runtime.h>

#define FDIM 1024
#define CDIM 64
#define NROWS 65536
#define RPB 8                         // warps (rows in flight) per block
#define NTHREADS (RPB * 32)
#define NBLOCKS 444                   // 148 SMs x 3 blocks: one resident wave
#define NWARPS_TOTAL (NBLOCKS * RPB)
#define PADF 1280                     // padded sorted row length (<=1216 used)

#define NEG_INF __int_as_float(0xff800000)

// Scratch (no allocations allowed)
__device__ int          g_meta[FDIM];       // seg | (padded pos << 8)
__device__ int          g_pstart[CDIM + 1]; // padded group boundaries
__device__ double       g_acc[64];          // interleaved loss accumulators (zero-init)
__device__ int          g_done;             // finished-block counter (zero-init)
__device__ volatile int g_flag;             // setup-done flag (zero-init)

__global__ void __launch_bounds__(NTHREADS, 3) mix_kernel(
    const float* __restrict__ logits,
    const int*   __restrict__ labels,
    const float* __restrict__ mask,
    float*       __restrict__ out)
{
    __shared__ float sslice[RPB][PADF];   // 40 KB: padded group-sorted rows
    __shared__ int   spstart[CDIM + 1];
    __shared__ int   scnt[CDIM];
    __shared__ int   s_w0sum;

    const int t    = threadIdx.x;
    const int lane = t & 31;
    const int w    = t >> 5;

    // ---------------- Setup (block 0) / wait (others) ----------------
    if (blockIdx.x == 0) {
        if (t < CDIM) scnt[t] = 0;
        __syncthreads();

        int segs[4], ranks[4];
#pragma unroll
        for (int i = 0; i < 4; i++) {
            int f = t + 256 * i;
            const float4* mrow = reinterpret_cast<const float4*>(mask + f * CDIM);
            float acc = 0.0f;
#pragma unroll
            for (int q = 0; q < 16; q++) {
                float4 m = mrow[q];
                float c0 = (float)(4 * q);
                acc = fmaf(m.x, c0,        acc);
                acc = fmaf(m.y, c0 + 1.0f, acc);
                acc = fmaf(m.z, c0 + 2.0f, acc);
                acc = fmaf(m.w, c0 + 3.0f, acc);
            }
            segs[i]  = (int)(acc + 0.5f);
            ranks[i] = atomicAdd(&scnt[segs[i]], 1);
        }
        __syncthreads();

        // exclusive prefix of padded counts (groups padded to multiple of 4)
        int v = 0, sc = 0;
        if (t < CDIM) {
            v = (scnt[t] + 3) & ~3;
            sc = v;
#pragma unroll
            for (int o = 1; o < 32; o <<= 1) {
                int n = __shfl_up_sync(0xFFFFFFFFu, sc, o);
                if (lane >= o) sc += n;
            }
            if (t == 31) s_w0sum = sc;
        }
        __syncthreads();
        if (t < CDIM) {
            int base = sc - v + ((t >= 32) ? s_w0sum : 0);
            spstart[t] = base;
            g_pstart[t] = base;
            if (t == 63) { spstart[64] = base + v; g_pstart[64] = base + v; }
        }
        __syncthreads();

#pragma unroll
        for (int i = 0; i < 4; i++) {
            int f = t + 256 * i;
            int pos = spstart[segs[i]] + ranks[i];
            g_meta[f] = segs[i] | (pos << 8);
        }
        __threadfence();
        __syncthreads();
        if (t == 0) g_flag = 1;
    } else {
        if (t == 0) { while (g_flag == 0) {} }
        __syncthreads();
        __threadfence();
        if (t <= CDIM) spstart[t] = g_pstart[t];
        __syncthreads();
    }

    // ---------------- Per-warp prologue ----------------
    uint4 m0 = reinterpret_cast<const uint4*>(g_meta)[lane];
    uint4 m1 = reinterpret_cast<const uint4*>(g_meta)[lane + 32];
    uint4 m2 = reinterpret_cast<const uint4*>(g_meta)[lane + 64];
    uint4 m3 = reinterpret_cast<const uint4*>(g_meta)[lane + 96];
    uint4 m4 = reinterpret_cast<const uint4*>(g_meta)[lane + 128];
    uint4 m5 = reinterpret_cast<const uint4*>(g_meta)[lane + 160];
    uint4 m6 = reinterpret_cast<const uint4*>(g_meta)[lane + 192];
    uint4 m7 = reinterpret_cast<const uint4*>(g_meta)[lane + 224];

    float* my = sslice[w];
    float4* my4 = reinterpret_cast<float4*>(my);
    // init whole slice to -inf once: pads stay -inf forever
    for (int i = lane; i < PADF / 4; i += 32)
        my4[i] = make_float4(NEG_INF, NEG_INF, NEG_INF, NEG_INF);
    __syncwarp();

    const int a0 = spstart[lane],      b0 = spstart[lane + 1];
    const int a1 = spstart[lane + 32], b1 = spstart[lane + 33];

    // ---------------- Row loop ----------------
    for (int row = blockIdx.x * RPB + w; row < NROWS; row += NWARPS_TOTAL) {
        const int label = __ldg(&labels[row]);
        const float4* rp = reinterpret_cast<const float4*>(logits + (size_t)row * FDIM);
        float4 v0 = rp[lane];
        float4 v1 = rp[lane + 32];
        float4 v2 = rp[lane + 64];
        float4 v3 = rp[lane + 96];
        float4 v4 = rp[lane + 128];
        float4 v5 = rp[lane + 160];
        float4 v6 = rp[lane + 192];
        float4 v7 = rp[lane + 224];

        float tot = 0.0f, ls = 0.0f;

#define DO_CHUNK(VV, MM)                                                     \
        {                                                                    \
            { float e = __expf(VV.x); tot += e;                              \
              if ((int)(MM.x & 0xFFu) == label) ls += e;                     \
              my[(MM.x >> 8) & 2047u] = VV.x; }                              \
            { float e = __expf(VV.y); tot += e;                              \
              if ((int)(MM.y & 0xFFu) == label) ls += e;                     \
              my[(MM.y >> 8) & 2047u] = VV.y; }                              \
            { float e = __expf(VV.z); tot += e;                              \
              if ((int)(MM.z & 0xFFu) == label) ls += e;                     \
              my[(MM.z >> 8) & 2047u] = VV.z; }                              \
            { float e = __expf(VV.w); tot += e;                              \
              if ((int)(MM.w & 0xFFu) == label) ls += e;                     \
              my[(MM.w >> 8) & 2047u] = VV.w; }                              \
        }
        DO_CHUNK(v0, m0) DO_CHUNK(v1, m1) DO_CHUNK(v2, m2) DO_CHUNK(v3, m3)
        DO_CHUNK(v4, m4) DO_CHUNK(v5, m5) DO_CHUNK(v6, m6) DO_CHUNK(v7, m7)
#undef DO_CHUNK

        __syncwarp();   // scatter -> scan

        // aligned, maskless segment max: lane handles groups lane, lane+32
        float gm0 = NEG_INF, gm1 = NEG_INF;
        for (int q = a0 >> 2; q < (b0 >> 2); q++) {
            float4 c = my4[q];
            gm0 = fmaxf(gm0, fmaxf(fmaxf(c.x, c.y), fmaxf(c.z, c.w)));
        }
        for (int q = a1 >> 2; q < (b1 >> 2); q++) {
            float4 c = my4[q];
            gm1 = fmaxf(gm1, fmaxf(fmaxf(c.x, c.y), fmaxf(c.z, c.w)));
        }
        __syncwarp();   // scan done before next row's scatter

        float cand = (label < 32) ? gm0 : gm1;
        float gml  = __shfl_sync(0xFFFFFFFFu, cand, label & 31);

        float csum = __expf(gm0) + __expf(gm1);
#pragma unroll
        for (int o = 16; o; o >>= 1) {
            csum += __shfl_xor_sync(0xFFFFFFFFu, csum, o);
            tot  += __shfl_xor_sync(0xFFFFFFFFu, tot, o);
            ls   += __shfl_xor_sync(0xFFFFFFFFu, ls, o);
        }

        if (lane == 0) {
            float ce  = logf(csum) - gml;
            float nll = logf(tot) - logf(ls);
            atomicAdd(&g_acc[row & 63], (double)(0.5f * (ce + nll)));
        }
    }

    // ---------------- Fused finalize (last block) ----------------
    __syncthreads();
    if (t == 0) {
        __threadfence();
        if (atomicAdd(&g_done, 1) == NBLOCKS - 1) {
            __threadfence();
            double s = 0.0;
#pragma unroll
            for (int i = 0; i < 64; i++) s += g_acc[i];
            out[0] = (float)(s / (double)NROWS);
            // reset for the next graph replay
#pragma unroll
            for (int i = 0; i < 64; i++) g_acc[i] = 0.0;
            g_done = 0;
            __threadfence();
            g_flag = 0;
        }
    }
}

extern "C" void kernel_launch(void* const* d_in, const int* in_sizes, int n_in,
                              void* d_out, int out_size) {
    const float* logits = (const float*)d_in[0];  // [32, 2048, 1024] f32
    const int*   labels = (const int*)d_in[1];    // [32, 2048] i32
    const float* mask   = (const float*)d_in[2];  // [1024, 64] f32

    mix_kernel<<<NBLOCKS, NTHREADS>>>(logits, labels, mask, (float*)d_out);
}

// round 9
// speedup vs baseline: 1.0805x; 1.0805x over previous
#include <cuda_runtime.h>

#define FDIM 1024
#define CDIM 64
#define NROWS 65536
#define RPB 8                          // warps (row streams) per block
#define NTHREADS (RPB * 32)
#define NBLOCKS (148 * 4)              // persistent: 4 blocks/SM
#define NWARPS_TOTAL (NBLOCKS * RPB)
#define PADF 1216                      // padded sorted row length (max 1024+64*3)

#define NEG_INF __int_as_float(0xff800000)

// Scratch (no allocations allowed)
__device__ int    g_meta[FDIM];        // seg | (padded pos << 8)
__device__ int    g_pstart[CDIM + 1];  // padded group boundaries
__device__ double g_acc[64];           // interleaved loss accumulators

// ---------------------------------------------------------------------------
// Setup <<<1, 256>>>: seg via one-hot dot product, ranks via smem atomics,
// padded-group prefix scan, packed meta. Also zeroes accumulators.
// ---------------------------------------------------------------------------
__global__ void setup_kernel(const float* __restrict__ mask) {
    __shared__ int scnt[CDIM];
    __shared__ int sbase[CDIM];
    __shared__ int s_w0sum;
    const int t = threadIdx.x;
    const int lane = t & 31;

    if (t < CDIM) scnt[t] = 0;
    __syncthreads();

    int segs[4], ranks[4];
#pragma unroll
    for (int i = 0; i < 4; i++) {
        int f = t + 256 * i;
        const float4* mrow = reinterpret_cast<const float4*>(mask + f * CDIM);
        float acc = 0.0f;
#pragma unroll
        for (int q = 0; q < 16; q++) {
            float4 m = mrow[q];
            float c0 = (float)(4 * q);
            acc = fmaf(m.x, c0,        acc);
            acc = fmaf(m.y, c0 + 1.0f, acc);
            acc = fmaf(m.z, c0 + 2.0f, acc);
            acc = fmaf(m.w, c0 + 3.0f, acc);
        }
        segs[i]  = (int)(acc + 0.5f);
        ranks[i] = atomicAdd(&scnt[segs[i]], 1);
    }
    __syncthreads();

    // exclusive prefix of 4-padded counts (threads 0..63 = warps 0,1)
    int v = 0, sc = 0;
    if (t < CDIM) {
        v = (scnt[t] + 3) & ~3;
        sc = v;
#pragma unroll
        for (int o = 1; o < 32; o <<= 1) {
            int n = __shfl_up_sync(0xFFFFFFFFu, sc, o);
            if (lane >= o) sc += n;
        }
        if (t == 31) s_w0sum = sc;
    }
    __syncthreads();
    if (t < CDIM) {
        int base = sc - v + ((t >= 32) ? s_w0sum : 0);
        sbase[t] = base;
        g_pstart[t] = base;
        if (t == 63) g_pstart[64] = base + v;
        g_acc[t] = 0.0;                 // re-zero every launch (graph replays)
    }
    __syncthreads();

#pragma unroll
    for (int i = 0; i < 4; i++) {
        int f = t + 256 * i;
        int pos = sbase[segs[i]] + ranks[i];
        g_meta[f] = segs[i] | (pos << 8);
    }
}

// ---------------------------------------------------------------------------
// Main: persistent, warp-per-row-stream. Per row: 8 batched float4 LDG,
// exp + predicated label-sum + scatter into this warp's padded group-sorted
// smem slice, then aligned maskless float4 segment-max scan.
// ---------------------------------------------------------------------------
__global__ void __launch_bounds__(NTHREADS, 4) mix_kernel(
    const float* __restrict__ logits,
    const int*   __restrict__ labels)
{
    __shared__ float sslice[RPB][PADF];     // 38 KB padded sorted rows
    __shared__ uint4 smeta[FDIM / 4];       // 4 KB packed meta
    __shared__ int   spstart[CDIM + 1];

    const int t    = threadIdx.x;
    const int lane = t & 31;
    const int w    = t >> 5;

    // block prologue
    smeta[t] = reinterpret_cast<const uint4*>(g_meta)[t];
    if (t <= CDIM) spstart[t] = g_pstart[t];
    __syncthreads();

    float*  my  = sslice[w];
    float4* my4 = reinterpret_cast<float4*>(my);
    for (int i = lane; i < PADF / 4; i += 32)      // pads stay -inf forever
        my4[i] = make_float4(NEG_INF, NEG_INF, NEG_INF, NEG_INF);
    __syncwarp();

    const int a0 = spstart[lane],      b0 = spstart[lane + 1];
    const int a1 = spstart[lane + 32], b1 = spstart[lane + 33];

    for (int row = blockIdx.x * RPB + w; row < NROWS; row += NWARPS_TOTAL) {
        const int label = __ldg(&labels[row]);
        const float4* rp = reinterpret_cast<const float4*>(logits + (size_t)row * FDIM);
        float4 v0 = rp[lane];
        float4 v1 = rp[lane + 32];
        float4 v2 = rp[lane + 64];
        float4 v3 = rp[lane + 96];
        float4 v4 = rp[lane + 128];
        float4 v5 = rp[lane + 160];
        float4 v6 = rp[lane + 192];
        float4 v7 = rp[lane + 224];

        float tot = 0.0f, ls = 0.0f;

#define DO_CHUNK(VV, CI)                                                     \
        {                                                                    \
            uint4 m = smeta[lane + 32 * (CI)];                               \
            { float e = __expf(VV.x); tot += e;                              \
              if ((int)(m.x & 0xFFu) == label) ls += e;                      \
              my[(m.x >> 8) & 2047u] = VV.x; }                               \
            { float e = __expf(VV.y); tot += e;                              \
              if ((int)(m.y & 0xFFu) == label) ls += e;                      \
              my[(m.y >> 8) & 2047u] = VV.y; }                               \
            { float e = __expf(VV.z); tot += e;                              \
              if ((int)(m.z & 0xFFu) == label) ls += e;                      \
              my[(m.z >> 8) & 2047u] = VV.z; }                               \
            { float e = __expf(VV.w); tot += e;                              \
              if ((int)(m.w & 0xFFu) == label) ls += e;                      \
              my[(m.w >> 8) & 2047u] = VV.w; }                               \
        }
        DO_CHUNK(v0, 0) DO_CHUNK(v1, 1) DO_CHUNK(v2, 2) DO_CHUNK(v3, 3)
        DO_CHUNK(v4, 4) DO_CHUNK(v5, 5) DO_CHUNK(v6, 6) DO_CHUNK(v7, 7)
#undef DO_CHUNK

        __syncwarp();   // scatter -> scan

        // aligned maskless segment max: lane handles groups lane, lane+32
        float gm0 = NEG_INF, gm1 = NEG_INF;
        for (int q = a0 >> 2; q < (b0 >> 2); q++) {
            float4 c = my4[q];
            gm0 = fmaxf(gm0, fmaxf(fmaxf(c.x, c.y), fmaxf(c.z, c.w)));
        }
        for (int q = a1 >> 2; q < (b1 >> 2); q++) {
            float4 c = my4[q];
            gm1 = fmaxf(gm1, fmaxf(fmaxf(c.x, c.y), fmaxf(c.z, c.w)));
        }
        __syncwarp();   // scan done before next row's scatter

        float cand = (label < 32) ? gm0 : gm1;
        float gml  = __shfl_sync(0xFFFFFFFFu, cand, label & 31);

        float csum = __expf(gm0) + __expf(gm1);
#pragma unroll
        for (int o = 16; o; o >>= 1) {
            csum += __shfl_xor_sync(0xFFFFFFFFu, csum, o);
            tot  += __shfl_xor_sync(0xFFFFFFFFu, tot, o);
            ls   += __shfl_xor_sync(0xFFFFFFFFu, ls, o);
        }

        if (lane == 0) {
            float ce  = logf(csum) - gml;        // lse(coarse_max) - gmax[label]
            float nll = logf(tot) - logf(ls);    // log(total) - log(group_sum)
            atomicAdd(&g_acc[row & 63], (double)(0.5f * (ce + nll)));
        }
    }
}

// ---------------------------------------------------------------------------
// Finalize: mean over rows -> d_out[0]
// ---------------------------------------------------------------------------
__global__ void finalize_kernel(float* __restrict__ out) {
    double s = 0.0;
#pragma unroll
    for (int i = 0; i < 64; i++) s += g_acc[i];
    out[0] = (float)(s / (double)NROWS);
}

extern "C" void kernel_launch(void* const* d_in, const int* in_sizes, int n_in,
                              void* d_out, int out_size) {
    const float* logits = (const float*)d_in[0];  // [32, 2048, 1024] f32
    const int*   labels = (const int*)d_in[1];    // [32, 2048] i32
    const float* mask   = (const float*)d_in[2];  // [1024, 64] f32

    setup_kernel<<<1, 256>>>(mask);
    mix_kernel<<<NBLOCKS, NTHREADS>>>(logits, labels);
    finalize_kernel<<<1, 1>>>((float*)d_out);
}